// round 11
// baseline (speedup 1.0000x reference)
#include <cuda_runtime.h>
#include <cuda_bf16.h>
#include <cstdint>

// Shapes (fixed by the problem)
#define BSZ    2
#define NN     384
#define DATOM  512
#define DPAIR  128
#define DHID   32
#define NROWS  (BSZ*NN)          // 768
#define PSLICE (NROWS*64)        // 49152

// Scratch (no cudaMalloc allowed)
__device__ float g_ab[NROWS * 64];            // bv half used by stage3 (cols 32..63)
__device__ float g_t [NROWS * DPAIR * DHID];  // t rows stored at qperm'd p positions
__device__ float g_part[4 * PSLICE];          // stage1 split-k partials

// involution on p%32: l = nt*8 + 2*tg + e  <->  q = 8*tg + 2*nt + e
__device__ __forceinline__ int qperm(int l) {
    return ((l & 7) >> 1) * 8 + (l >> 3) * 2 + (l & 1);
}

// ---------------- f32x2 packed-FMA helpers (sm_103a) ----------------
__device__ __forceinline__ unsigned long long pack2(float x, float y) {
    unsigned long long r;
    asm("mov.b64 %0,{%1,%2};" : "=l"(r) : "f"(x), "f"(y));
    return r;
}
__device__ __forceinline__ void unpack2(unsigned long long v, float& x, float& y) {
    asm("mov.b64 {%0,%1},%2;" : "=f"(x), "=f"(y) : "l"(v));
}
__device__ __forceinline__ void fma2(unsigned long long& d,
                                     unsigned long long a,
                                     unsigned long long b) {
    asm("fma.rn.f32x2 %0,%1,%2,%0;" : "+l"(d) : "l"(a), "l"(b));
}

// ---------------- tf32 / async helpers ----------------
__device__ __forceinline__ uint32_t f2tf32(float f) {
    uint32_t u;
    asm("cvt.rna.tf32.f32 %0, %1;" : "=r"(u) : "f"(f));
    return u;
}
__device__ __forceinline__ void mma_tf32(float c[4], const uint32_t a[4],
                                         const uint32_t b[2]) {
    asm("mma.sync.aligned.m16n8k8.row.col.f32.tf32.tf32.f32 "
        "{%0,%1,%2,%3}, {%4,%5,%6,%7}, {%8,%9}, {%0,%1,%2,%3};"
        : "+f"(c[0]), "+f"(c[1]), "+f"(c[2]), "+f"(c[3])
        : "r"(a[0]), "r"(a[1]), "r"(a[2]), "r"(a[3]), "r"(b[0]), "r"(b[1]));
}
__device__ __forceinline__ uint32_t smem_u32(const void* p) {
    uint32_t a;
    asm("{ .reg .u64 t; cvta.to.shared.u64 t, %1; cvt.u32.u64 %0, t; }" : "=r"(a) : "l"(p));
    return a;
}
#define CP_ASYNC16(dst, src) \
    asm volatile("cp.async.ca.shared.global [%0], [%1], 16;" :: "r"(dst), "l"(src))
#define CP_COMMIT() asm volatile("cp.async.commit_group;")
#define CP_WAIT0()  asm volatile("cp.async.wait_group 0;")

// ---------------- Stage 1a: split-k partial GEMM ----------------
// grid (96 rowtiles, 4 kslices), block 256. Block: 8 rows x 64 h x 128 k.
__global__ __launch_bounds__(256) void stage1a(
    const float* __restrict__ m, const float* __restrict__ W_in)
{
    __shared__ __align__(16) float m_s[8 * 128];
    __shared__ __align__(16) float w_s[64 * 132];
    int tid = threadIdx.x;
    int rbase = blockIdx.x * 8;
    int kc = blockIdx.y * 128;

    {
        int r = tid >> 5, c = (tid & 31) * 4;
        *(float4*)&m_s[r * 128 + c] =
            *(const float4*)(m + (size_t)(rbase + r) * 512 + kc + c);
    }
#pragma unroll
    for (int k = 0; k < 8; k++) {
        int idx4 = tid + k * 256;
        int h = idx4 >> 5, c = (idx4 & 31) * 4;
        *(float4*)&w_s[h * 132 + c] =
            *(const float4*)(W_in + (size_t)h * 512 + kc + c);
    }
    __syncthreads();

    int h = tid & 63, rg = tid >> 6;
    float acc0 = 0.f, acc1 = 0.f;
#pragma unroll
    for (int x = 0; x < 32; x++) {
        float4 wv = *(const float4*)&w_s[h * 132 + x * 4];
        float4 m0 = *(const float4*)&m_s[rg * 128 + x * 4];
        float4 m1 = *(const float4*)&m_s[(rg + 4) * 128 + x * 4];
        acc0 = fmaf(wv.x, m0.x, acc0); acc0 = fmaf(wv.y, m0.y, acc0);
        acc0 = fmaf(wv.z, m0.z, acc0); acc0 = fmaf(wv.w, m0.w, acc0);
        acc1 = fmaf(wv.x, m1.x, acc1); acc1 = fmaf(wv.y, m1.y, acc1);
        acc1 = fmaf(wv.z, m1.z, acc1); acc1 = fmaf(wv.w, m1.w, acc1);
    }
    float* dst = g_part + (size_t)blockIdx.y * PSLICE;
    dst[(size_t)(rbase + rg) * 64 + h] = acc0;
    dst[(size_t)(rbase + rg + 4) * 64 + h] = acc1;
}

// ---------------- Stage 2 (fused reduce): t[row,p,y] = sum_x a[row,x]*Wo[p,x,y] ----------------
// grid (8 p-tiles, 24 row-tiles), block 256. Block: 16 p x 32 rows x 32 y.
// Reduces g_part -> a_s internally; blockIdx.x==0 also writes the bv half to g_ab.
// t rows are written to QPERM'd p positions so stage3's epilogue is contiguous.
__global__ __launch_bounds__(256) void stage2_t(
    const float* __restrict__ W_out, const float* __restrict__ b_in,
    const float* __restrict__ op_mask)
{
    __shared__ __align__(16) float w_s[16 * 1024];   // 64 KB
    __shared__ __align__(16) float a_s[32 * 32];
    int tid = threadIdx.x;
    int pbase = blockIdx.x * 16;
    int rbase = blockIdx.y * 32;

    const float4* wsrc = (const float4*)(W_out + (size_t)pbase * 1024);
    float4* wdst = (float4*)w_s;
#pragma unroll
    for (int k = 0; k < 16; k++) wdst[tid + k * 256] = wsrc[tid + k * 256];

    // a-half reduce: 32 rows x 32 cols
#pragma unroll
    for (int k = 0; k < 4; k++) {
        int e = tid + k * 256;           // 0..1023
        int r = e >> 5, c = e & 31;
        int gi = (rbase + r) * 64 + c;
        float s = g_part[gi] + g_part[gi + PSLICE]
                + g_part[gi + 2 * PSLICE] + g_part[gi + 3 * PSLICE];
        a_s[r * 32 + c] = (s + b_in[c]) * op_mask[rbase + r];
    }
    // bv-half reduce + write (one block column only)
    if (blockIdx.x == 0) {
#pragma unroll
        for (int k = 0; k < 4; k++) {
            int e = tid + k * 256;
            int r = e >> 5, c = e & 31;
            int gi = (rbase + r) * 64 + 32 + c;
            float s = g_part[gi] + g_part[gi + PSLICE]
                    + g_part[gi + 2 * PSLICE] + g_part[gi + 3 * PSLICE];
            g_ab[gi] = (s + b_in[32 + c]) * op_mask[rbase + r];
        }
    }
    __syncthreads();

    int y = tid & 31, q = tid >> 5;
    unsigned long long w2a[16], w2b[16];
#pragma unroll
    for (int x2 = 0; x2 < 16; x2++) {
        w2a[x2] = pack2(w_s[q * 1024 + (2 * x2 + 0) * 32 + y],
                        w_s[q * 1024 + (2 * x2 + 1) * 32 + y]);
        w2b[x2] = pack2(w_s[(q + 8) * 1024 + (2 * x2 + 0) * 32 + y],
                        w_s[(q + 8) * 1024 + (2 * x2 + 1) * 32 + y]);
    }
    // permuted destination rows (within each 32-block of p)
    int p0r = pbase + q,     p1r = pbase + q + 8;
    int pp0 = (p0r & ~31) | qperm(p0r & 31);
    int pp1 = (p1r & ~31) | qperm(p1r & 31);
    float* dst0 = g_t + (size_t)rbase * 4096 + (size_t)pp0 * 32 + y;
    float* dst1 = g_t + (size_t)rbase * 4096 + (size_t)pp1 * 32 + y;
#pragma unroll 2
    for (int r = 0; r < 32; r++) {
        unsigned long long acc0 = 0ull, acc1 = 0ull;
#pragma unroll
        for (int xc = 0; xc < 8; xc++) {
            ulonglong2 a2 = *(const ulonglong2*)&a_s[r * 32 + xc * 4];
            fma2(acc0, a2.x, w2a[2 * xc + 0]);
            fma2(acc0, a2.y, w2a[2 * xc + 1]);
            fma2(acc1, a2.x, w2b[2 * xc + 0]);
            fma2(acc1, a2.y, w2b[2 * xc + 1]);
        }
        float lo0, hi0, lo1, hi1;
        unpack2(acc0, lo0, hi0); unpack2(acc1, lo1, hi1);
        dst0[(size_t)r * 4096] = __uint_as_float(f2tf32(lo0 + hi0));
        dst1[(size_t)r * 4096] = __uint_as_float(f2tf32(lo1 + hi1));
    }
}

// ---------------- Stage 3 (warp MMA, tf32, cp.async) — R6 mainloop, STG.128 epilogue ----------------
// grid (2, NN, BSZ): each CTA = 3 j-chunks of 64 for one (b,i).
// Warp grid 2(j) x 4(p): warp tile 32j x 32p. t_s fill CONTIGUOUS (g_t pre-permuted).
// Logical B-col l of warp wn maps to physical p = wn*32 + qperm(l) -> each thread
// owns 8 contiguous physical p at p0 = wn*32 + 8*tg.
#define S3PAD 36
__global__ __launch_bounds__(256, 3) void stage3_mma(
    const float* __restrict__ b_out, const float* __restrict__ op_norm,
    float* __restrict__ out)
{
    __shared__ __align__(16) uint32_t t_s[128 * S3PAD];     // 18.4 KB (tf32 bits)
    __shared__ __align__(16) uint32_t a_s[2][64 * S3PAD];   // 2 x 9.2 KB (raw fp32 bv)
    __shared__ float bo_s[128];

    int tid = threadIdx.x;
    int half = blockIdx.x;        // 0/1: j-chunks 0..2 / 3..5
    int i = blockIdx.y;
    int b = blockIdx.z;
    int row = b * NN + i;

    uint32_t t_base = smem_u32(t_s);
    uint32_t a_base = smem_u32(a_s);

    // async fill t row — CONTIGUOUS (permutation already applied by stage2)
    const float* tsrc = g_t + (size_t)row * 4096;
#pragma unroll
    for (int k = 0; k < 4; k++) {
        int idx4 = tid + k * 256;
        int e = idx4 * 4, p = e >> 5, y = e & 31;
        CP_ASYNC16(t_base + (uint32_t)(p * S3PAD + y) * 4, tsrc + e);
    }
    // async fill a_s buf0 (chunk 0 of this half): raw fp32 bv
    const float* absrc = g_ab + (size_t)(b * NN) * 64;
    int jb0 = half * 192;
#pragma unroll
    for (int k = 0; k < 2; k++) {
        int idx4 = tid + k * 256;
        int j = idx4 >> 3, c = (idx4 & 7) * 4;
        CP_ASYNC16(a_base + (uint32_t)(j * S3PAD + c) * 4,
                   absrc + (size_t)(jb0 + j) * 64 + 32 + c);
    }
    CP_COMMIT();
    if (tid < 128) bo_s[tid] = b_out[tid];

    int wid = tid >> 5, lane = tid & 31;
    int g = lane >> 2, tg = lane & 3;
    int wm = wid & 1;          // j block of 32 (within 64-chunk)
    int wn = wid >> 1;         // p block of 32
    float norm = op_norm[b];
    int p0 = wn * 32 + 8 * tg; // this thread's 8 contiguous PHYSICAL p

    __syncthreads();           // bo_s visible
    float bz[8];
#pragma unroll
    for (int k = 0; k < 8; k++) bz[k] = bo_s[p0 + k] * norm;

    for (int jc = 0; jc < 3; jc++) {
        int jbase = half * 192 + jc * 64;
        int buf = jc & 1;
        CP_WAIT0();
        __syncthreads();   // buf ready; all warps done with prev chunk (other buf)

        if (jc < 2) {      // prefetch next chunk into other buffer
            uint32_t dstb = a_base + (uint32_t)((buf ^ 1) * 64 * S3PAD) * 4;
#pragma unroll
            for (int k = 0; k < 2; k++) {
                int idx4 = tid + k * 256;
                int j = idx4 >> 3, c = (idx4 & 7) * 4;
                CP_ASYNC16(dstb + (uint32_t)(j * S3PAD + c) * 4,
                           absrc + (size_t)(jbase + 64 + j) * 64 + 32 + c);
            }
            CP_COMMIT();
        } else {
            CP_COMMIT();   // keep wait_group balanced
        }

        const uint32_t* ab = a_s[buf];
        float acc[2][4][4];
#pragma unroll
        for (int mt = 0; mt < 2; mt++)
#pragma unroll
            for (int nt = 0; nt < 4; nt++)
#pragma unroll
                for (int r = 0; r < 4; r++) acc[mt][nt][r] = 0.f;

#pragma unroll
        for (int ks = 0; ks < 4; ks++) {
            int kk = ks * 8;
            uint32_t af[2][4];
#pragma unroll
            for (int mt = 0; mt < 2; mt++) {
                int r0 = wm * 32 + mt * 16;
                af[mt][0] = f2tf32(__uint_as_float(ab[(r0 + g) * S3PAD + kk + tg]));
                af[mt][1] = f2tf32(__uint_as_float(ab[(r0 + 8 + g) * S3PAD + kk + tg]));
                af[mt][2] = f2tf32(__uint_as_float(ab[(r0 + g) * S3PAD + kk + tg + 4]));
                af[mt][3] = f2tf32(__uint_as_float(ab[(r0 + 8 + g) * S3PAD + kk + tg + 4]));
            }
            uint32_t bf[4][2];
#pragma unroll
            for (int nt = 0; nt < 4; nt++) {
                int cc = wn * 32 + nt * 8 + g;
                bf[nt][0] = t_s[cc * S3PAD + kk + tg];
                bf[nt][1] = t_s[cc * S3PAD + kk + tg + 4];
            }
#pragma unroll
            for (int mt = 0; mt < 2; mt++)
#pragma unroll
                for (int nt = 0; nt < 4; nt++)
                    mma_tf32(acc[mt][nt], af[mt], bf[nt]);
        }

        // epilogue: physical col of acc[mt][nt][{0,1}] (row j0) / [{2,3}] (row j0+8)
        // is p0 + 2*nt + e  ->  two contiguous float4 per row, STG.128.
        size_t obase = ((size_t)row * NN + jbase) * DPAIR;
#pragma unroll
        for (int mt = 0; mt < 2; mt++) {
            int j0 = wm * 32 + mt * 16 + g;
            float* r0p = out + obase + (size_t)j0 * DPAIR + p0;
            float* r1p = out + obase + (size_t)(j0 + 8) * DPAIR + p0;
            float4 v;
            v.x = fmaf(acc[mt][0][0], norm, bz[0]);
            v.y = fmaf(acc[mt][0][1], norm, bz[1]);
            v.z = fmaf(acc[mt][1][0], norm, bz[2]);
            v.w = fmaf(acc[mt][1][1], norm, bz[3]);
            __stcs((float4*)r0p, v);
            v.x = fmaf(acc[mt][2][0], norm, bz[4]);
            v.y = fmaf(acc[mt][2][1], norm, bz[5]);
            v.z = fmaf(acc[mt][3][0], norm, bz[6]);
            v.w = fmaf(acc[mt][3][1], norm, bz[7]);
            __stcs((float4*)(r0p + 4), v);
            v.x = fmaf(acc[mt][0][2], norm, bz[0]);
            v.y = fmaf(acc[mt][0][3], norm, bz[1]);
            v.z = fmaf(acc[mt][1][2], norm, bz[2]);
            v.w = fmaf(acc[mt][1][3], norm, bz[3]);
            __stcs((float4*)r1p, v);
            v.x = fmaf(acc[mt][2][2], norm, bz[4]);
            v.y = fmaf(acc[mt][2][3], norm, bz[5]);
            v.z = fmaf(acc[mt][3][2], norm, bz[6]);
            v.w = fmaf(acc[mt][3][3], norm, bz[7]);
            __stcs((float4*)(r1p + 4), v);
        }
    }
}

// ---------------- launch ----------------
extern "C" void kernel_launch(void* const* d_in, const int* in_sizes, int n_in,
                              void* d_out, int out_size)
{
    const float* m       = (const float*)d_in[0];
    const float* op_mask = (const float*)d_in[1];
    const float* op_norm = (const float*)d_in[2];
    const float* W_in    = (const float*)d_in[3];
    const float* b_in    = (const float*)d_in[4];
    const float* W_out   = (const float*)d_in[5];
    const float* b_out   = (const float*)d_in[6];
    float* out = (float*)d_out;

    stage1a<<<dim3(96, 4), 256>>>(m, W_in);
    stage2_t<<<dim3(8, 24), 256>>>(W_out, b_in, op_mask);
    stage3_mma<<<dim3(2, NN, BSZ), 256>>>(b_out, op_norm, out);
}

// round 12
// speedup vs baseline: 1.0681x; 1.0681x over previous
#include <cuda_runtime.h>
#include <cuda_bf16.h>
#include <cstdint>

// Shapes (fixed by the problem)
#define BSZ    2
#define NN     384
#define DATOM  512
#define DPAIR  128
#define DHID   32
#define NROWS  (BSZ*NN)          // 768
#define PSLICE (NROWS*64)        // 49152

// Scratch (no cudaMalloc allowed)
__device__ float g_ab[NROWS * 64];            // bv half used by stage3 (cols 32..63)
__device__ float g_t [NROWS * DPAIR * DHID];  // t[row][p][y] (tf32-rounded bits)
__device__ float g_part[4 * PSLICE];          // stage1 split-k partials

// ---------------- f32x2 packed-FMA helpers (sm_103a) ----------------
__device__ __forceinline__ unsigned long long pack2(float x, float y) {
    unsigned long long r;
    asm("mov.b64 %0,{%1,%2};" : "=l"(r) : "f"(x), "f"(y));
    return r;
}
__device__ __forceinline__ void unpack2(unsigned long long v, float& x, float& y) {
    asm("mov.b64 {%0,%1},%2;" : "=f"(x), "=f"(y) : "l"(v));
}
__device__ __forceinline__ void fma2(unsigned long long& d,
                                     unsigned long long a,
                                     unsigned long long b) {
    asm("fma.rn.f32x2 %0,%1,%2,%0;" : "+l"(d) : "l"(a), "l"(b));
}

// ---------------- tf32 / async helpers ----------------
__device__ __forceinline__ uint32_t f2tf32(float f) {
    uint32_t u;
    asm("cvt.rna.tf32.f32 %0, %1;" : "=r"(u) : "f"(f));
    return u;
}
__device__ __forceinline__ void mma_tf32(float c[4], const uint32_t a[4],
                                         const uint32_t b[2]) {
    asm("mma.sync.aligned.m16n8k8.row.col.f32.tf32.tf32.f32 "
        "{%0,%1,%2,%3}, {%4,%5,%6,%7}, {%8,%9}, {%0,%1,%2,%3};"
        : "+f"(c[0]), "+f"(c[1]), "+f"(c[2]), "+f"(c[3])
        : "r"(a[0]), "r"(a[1]), "r"(a[2]), "r"(a[3]), "r"(b[0]), "r"(b[1]));
}
__device__ __forceinline__ uint32_t smem_u32(const void* p) {
    uint32_t a;
    asm("{ .reg .u64 t; cvta.to.shared.u64 t, %1; cvt.u32.u64 %0, t; }" : "=r"(a) : "l"(p));
    return a;
}
#define CP_ASYNC16(dst, src) \
    asm volatile("cp.async.ca.shared.global [%0], [%1], 16;" :: "r"(dst), "l"(src))
#define CP_COMMIT() asm volatile("cp.async.commit_group;")
#define CP_WAIT0()  asm volatile("cp.async.wait_group 0;")

// ---------------- Stage 1a: split-k partial GEMM ----------------
// grid (96 rowtiles, 4 kslices), block 256. Block: 8 rows x 64 h x 128 k.
__global__ __launch_bounds__(256) void stage1a(
    const float* __restrict__ m, const float* __restrict__ W_in)
{
    __shared__ __align__(16) float m_s[8 * 128];
    __shared__ __align__(16) float w_s[64 * 132];
    int tid = threadIdx.x;
    int rbase = blockIdx.x * 8;
    int kc = blockIdx.y * 128;

    {
        int r = tid >> 5, c = (tid & 31) * 4;
        *(float4*)&m_s[r * 128 + c] =
            *(const float4*)(m + (size_t)(rbase + r) * 512 + kc + c);
    }
#pragma unroll
    for (int k = 0; k < 8; k++) {
        int idx4 = tid + k * 256;
        int h = idx4 >> 5, c = (idx4 & 31) * 4;
        *(float4*)&w_s[h * 132 + c] =
            *(const float4*)(W_in + (size_t)h * 512 + kc + c);
    }
    __syncthreads();

    int h = tid & 63, rg = tid >> 6;
    float acc0 = 0.f, acc1 = 0.f;
#pragma unroll
    for (int x = 0; x < 32; x++) {
        float4 wv = *(const float4*)&w_s[h * 132 + x * 4];
        float4 m0 = *(const float4*)&m_s[rg * 128 + x * 4];
        float4 m1 = *(const float4*)&m_s[(rg + 4) * 128 + x * 4];
        acc0 = fmaf(wv.x, m0.x, acc0); acc0 = fmaf(wv.y, m0.y, acc0);
        acc0 = fmaf(wv.z, m0.z, acc0); acc0 = fmaf(wv.w, m0.w, acc0);
        acc1 = fmaf(wv.x, m1.x, acc1); acc1 = fmaf(wv.y, m1.y, acc1);
        acc1 = fmaf(wv.z, m1.z, acc1); acc1 = fmaf(wv.w, m1.w, acc1);
    }
    float* dst = g_part + (size_t)blockIdx.y * PSLICE;
    dst[(size_t)(rbase + rg) * 64 + h] = acc0;
    dst[(size_t)(rbase + rg + 4) * 64 + h] = acc1;
}

// ---------------- Stage 2 (fused reduce): t[row,p,y] = sum_x a[row,x]*Wo[p,x,y] ----------------
// grid (8 p-tiles, 24 row-tiles), block 256. Block: 16 p x 32 rows x 32 y.
// Reduces g_part -> a_s internally; blockIdx.x==0 also writes the bv half to g_ab.
__global__ __launch_bounds__(256) void stage2_t(
    const float* __restrict__ W_out, const float* __restrict__ b_in,
    const float* __restrict__ op_mask)
{
    __shared__ __align__(16) float w_s[16 * 1024];   // 64 KB
    __shared__ __align__(16) float a_s[32 * 32];
    int tid = threadIdx.x;
    int pbase = blockIdx.x * 16;
    int rbase = blockIdx.y * 32;

    const float4* wsrc = (const float4*)(W_out + (size_t)pbase * 1024);
    float4* wdst = (float4*)w_s;
#pragma unroll
    for (int k = 0; k < 16; k++) wdst[tid + k * 256] = wsrc[tid + k * 256];

    // a-half reduce: 32 rows x 32 cols (same op order as old stage1b)
#pragma unroll
    for (int k = 0; k < 4; k++) {
        int e = tid + k * 256;           // 0..1023
        int r = e >> 5, c = e & 31;
        int gi = (rbase + r) * 64 + c;
        float s = g_part[gi] + g_part[gi + PSLICE]
                + g_part[gi + 2 * PSLICE] + g_part[gi + 3 * PSLICE];
        a_s[r * 32 + c] = (s + b_in[c]) * op_mask[rbase + r];
    }
    // bv-half reduce + write (one block column only)
    if (blockIdx.x == 0) {
#pragma unroll
        for (int k = 0; k < 4; k++) {
            int e = tid + k * 256;
            int r = e >> 5, c = e & 31;
            int gi = (rbase + r) * 64 + 32 + c;
            float s = g_part[gi] + g_part[gi + PSLICE]
                    + g_part[gi + 2 * PSLICE] + g_part[gi + 3 * PSLICE];
            g_ab[gi] = (s + b_in[32 + c]) * op_mask[rbase + r];
        }
    }
    __syncthreads();

    int y = tid & 31, q = tid >> 5;
    unsigned long long w2a[16], w2b[16];
#pragma unroll
    for (int x2 = 0; x2 < 16; x2++) {
        w2a[x2] = pack2(w_s[q * 1024 + (2 * x2 + 0) * 32 + y],
                        w_s[q * 1024 + (2 * x2 + 1) * 32 + y]);
        w2b[x2] = pack2(w_s[(q + 8) * 1024 + (2 * x2 + 0) * 32 + y],
                        w_s[(q + 8) * 1024 + (2 * x2 + 1) * 32 + y]);
    }
    float* dst0 = g_t + (size_t)rbase * 4096 + (size_t)(pbase + q) * 32 + y;
    float* dst1 = g_t + (size_t)rbase * 4096 + (size_t)(pbase + q + 8) * 32 + y;
#pragma unroll 2
    for (int r = 0; r < 32; r++) {
        unsigned long long acc0 = 0ull, acc1 = 0ull;
#pragma unroll
        for (int xc = 0; xc < 8; xc++) {
            ulonglong2 a2 = *(const ulonglong2*)&a_s[r * 32 + xc * 4];
            fma2(acc0, a2.x, w2a[2 * xc + 0]);
            fma2(acc0, a2.y, w2a[2 * xc + 1]);
            fma2(acc1, a2.x, w2b[2 * xc + 0]);
            fma2(acc1, a2.y, w2b[2 * xc + 1]);
        }
        float lo0, hi0, lo1, hi1;
        unpack2(acc0, lo0, hi0); unpack2(acc1, lo1, hi1);
        dst0[(size_t)r * 4096] = __uint_as_float(f2tf32(lo0 + hi0));
        dst1[(size_t)r * 4096] = __uint_as_float(f2tf32(lo1 + hi1));
    }
}

// ---------------- Stage 3 (warp MMA, tf32, cp.async pipelined) — R6 body, occ 4 ----------------
// grid (2, NN, BSZ): each CTA = 3 j-chunks of 64 for one (b,i).
// Warp grid 2(j) x 4(p): warp tile 32j x 32p. a_s double-buffered via cp.async.
// __launch_bounds__(256,4): cap regs at 64 -> 4 CTAs/SM (smem 37KB*4 fits).
#define S3PAD 36
__global__ __launch_bounds__(256, 4) void stage3_mma(
    const float* __restrict__ b_out, const float* __restrict__ op_norm,
    float* __restrict__ out)
{
    __shared__ __align__(16) uint32_t t_s[128 * S3PAD];     // 18.4 KB (tf32 bits)
    __shared__ __align__(16) uint32_t a_s[2][64 * S3PAD];   // 2 x 9.2 KB (raw fp32 bv)
    __shared__ float bo_s[128];

    int tid = threadIdx.x;
    int half = blockIdx.x;        // 0/1: j-chunks 0..2 / 3..5
    int i = blockIdx.y;
    int b = blockIdx.z;
    int row = b * NN + i;

    uint32_t t_base = smem_u32(t_s);
    uint32_t a_base = smem_u32(a_s);

    // async fill t row (16 KB, already tf32-rounded by stage2)
    const float* tsrc = g_t + (size_t)row * 4096;
#pragma unroll
    for (int k = 0; k < 4; k++) {
        int idx4 = tid + k * 256;
        int e = idx4 * 4, p = e >> 5, y = e & 31;
        CP_ASYNC16(t_base + (uint32_t)(p * S3PAD + y) * 4, tsrc + e);
    }
    // async fill a_s buf0 (chunk 0 of this half): raw fp32 bv
    const float* absrc = g_ab + (size_t)(b * NN) * 64;
    int jb0 = half * 192;
#pragma unroll
    for (int k = 0; k < 2; k++) {
        int idx4 = tid + k * 256;
        int j = idx4 >> 3, c = (idx4 & 7) * 4;
        CP_ASYNC16(a_base + (uint32_t)(j * S3PAD + c) * 4,
                   absrc + (size_t)(jb0 + j) * 64 + 32 + c);
    }
    CP_COMMIT();
    if (tid < 128) bo_s[tid] = b_out[tid];

    int wid = tid >> 5, lane = tid & 31;
    int g = lane >> 2, tg = lane & 3;
    int wm = wid & 1;          // j block of 32 (within 64-chunk)
    int wn = wid >> 1;         // p block of 32
    float norm = op_norm[b];

    for (int jc = 0; jc < 3; jc++) {
        int jbase = half * 192 + jc * 64;
        int buf = jc & 1;
        CP_WAIT0();
        __syncthreads();   // buf ready; all warps done with prev chunk (other buf)

        if (jc < 2) {      // prefetch next chunk into other buffer
            uint32_t dstb = a_base + (uint32_t)((buf ^ 1) * 64 * S3PAD) * 4;
#pragma unroll
            for (int k = 0; k < 2; k++) {
                int idx4 = tid + k * 256;
                int j = idx4 >> 3, c = (idx4 & 7) * 4;
                CP_ASYNC16(dstb + (uint32_t)(j * S3PAD + c) * 4,
                           absrc + (size_t)(jbase + 64 + j) * 64 + 32 + c);
            }
            CP_COMMIT();
        } else {
            CP_COMMIT();   // keep wait_group balanced
        }

        const uint32_t* ab = a_s[buf];
        float acc[2][4][4];
#pragma unroll
        for (int mt = 0; mt < 2; mt++)
#pragma unroll
            for (int nt = 0; nt < 4; nt++)
#pragma unroll
                for (int r = 0; r < 4; r++) acc[mt][nt][r] = 0.f;

#pragma unroll
        for (int ks = 0; ks < 4; ks++) {
            int kk = ks * 8;
            uint32_t af[2][4];
#pragma unroll
            for (int mt = 0; mt < 2; mt++) {
                int r0 = wm * 32 + mt * 16;
                af[mt][0] = f2tf32(__uint_as_float(ab[(r0 + g) * S3PAD + kk + tg]));
                af[mt][1] = f2tf32(__uint_as_float(ab[(r0 + 8 + g) * S3PAD + kk + tg]));
                af[mt][2] = f2tf32(__uint_as_float(ab[(r0 + g) * S3PAD + kk + tg + 4]));
                af[mt][3] = f2tf32(__uint_as_float(ab[(r0 + 8 + g) * S3PAD + kk + tg + 4]));
            }
            uint32_t bf[4][2];
#pragma unroll
            for (int nt = 0; nt < 4; nt++) {
                int cc = wn * 32 + nt * 8 + g;
                bf[nt][0] = t_s[cc * S3PAD + kk + tg];
                bf[nt][1] = t_s[cc * S3PAD + kk + tg + 4];
            }
#pragma unroll
            for (int mt = 0; mt < 2; mt++)
#pragma unroll
                for (int nt = 0; nt < 4; nt++)
                    mma_tf32(acc[mt][nt], af[mt], bf[nt]);
        }

        // epilogue: z = acc*norm + b_out[p]*norm (streaming stores)
        size_t obase = ((size_t)row * NN + jbase) * DPAIR;
#pragma unroll
        for (int mt = 0; mt < 2; mt++) {
            int j0 = wm * 32 + mt * 16 + g;
#pragma unroll
            for (int nt = 0; nt < 4; nt++) {
                int p = wn * 32 + nt * 8 + 2 * tg;
                float bz0 = bo_s[p] * norm, bz1 = bo_s[p + 1] * norm;
                float2 v0 = make_float2(fmaf(acc[mt][nt][0], norm, bz0),
                                        fmaf(acc[mt][nt][1], norm, bz1));
                float2 v1 = make_float2(fmaf(acc[mt][nt][2], norm, bz0),
                                        fmaf(acc[mt][nt][3], norm, bz1));
                __stcs((float2*)(out + obase + (size_t)j0 * DPAIR + p), v0);
                __stcs((float2*)(out + obase + (size_t)(j0 + 8) * DPAIR + p), v1);
            }
        }
    }
}

// ---------------- launch ----------------
extern "C" void kernel_launch(void* const* d_in, const int* in_sizes, int n_in,
                              void* d_out, int out_size)
{
    const float* m       = (const float*)d_in[0];
    const float* op_mask = (const float*)d_in[1];
    const float* op_norm = (const float*)d_in[2];
    const float* W_in    = (const float*)d_in[3];
    const float* b_in    = (const float*)d_in[4];
    const float* W_out   = (const float*)d_in[5];
    const float* b_out   = (const float*)d_in[6];
    float* out = (float*)d_out;

    stage1a<<<dim3(96, 4), 256>>>(m, W_in);
    stage2_t<<<dim3(8, 24), 256>>>(W_out, b_in, op_mask);
    stage3_mma<<<dim3(2, NN, BSZ), 256>>>(b_out, op_norm, out);
}

// round 13
// speedup vs baseline: 1.1300x; 1.0580x over previous
#include <cuda_runtime.h>
#include <cuda_bf16.h>
#include <cstdint>

// Shapes (fixed by the problem)
#define BSZ    2
#define NN     384
#define DATOM  512
#define DPAIR  128
#define DHID   32
#define NROWS  (BSZ*NN)          // 768
#define PSLICE (NROWS*64)        // 49152
#define NSLICE 8                 // split-k slices (64 k each)

// Scratch (no cudaMalloc allowed)
__device__ float g_ab[NROWS * 64];            // bv half used by stage3 (cols 32..63)
__device__ float g_t [NROWS * DPAIR * DHID];  // t[row][p][y] (tf32-rounded bits)
__device__ float g_part[NSLICE * PSLICE];     // stage1 split-k partials

// ---------------- f32x2 packed-FMA helpers (sm_103a) ----------------
__device__ __forceinline__ unsigned long long pack2(float x, float y) {
    unsigned long long r;
    asm("mov.b64 %0,{%1,%2};" : "=l"(r) : "f"(x), "f"(y));
    return r;
}
__device__ __forceinline__ void unpack2(unsigned long long v, float& x, float& y) {
    asm("mov.b64 {%0,%1},%2;" : "=f"(x), "=f"(y) : "l"(v));
}
__device__ __forceinline__ void fma2(unsigned long long& d,
                                     unsigned long long a,
                                     unsigned long long b) {
    asm("fma.rn.f32x2 %0,%1,%2,%0;" : "+l"(d) : "l"(a), "l"(b));
}

// ---------------- tf32 / async helpers ----------------
__device__ __forceinline__ uint32_t f2tf32(float f) {
    uint32_t u;
    asm("cvt.rna.tf32.f32 %0, %1;" : "=r"(u) : "f"(f));
    return u;
}
__device__ __forceinline__ void mma_tf32(float c[4], const uint32_t a[4],
                                         const uint32_t b[2]) {
    asm("mma.sync.aligned.m16n8k8.row.col.f32.tf32.tf32.f32 "
        "{%0,%1,%2,%3}, {%4,%5,%6,%7}, {%8,%9}, {%0,%1,%2,%3};"
        : "+f"(c[0]), "+f"(c[1]), "+f"(c[2]), "+f"(c[3])
        : "r"(a[0]), "r"(a[1]), "r"(a[2]), "r"(a[3]), "r"(b[0]), "r"(b[1]));
}
__device__ __forceinline__ uint32_t smem_u32(const void* p) {
    uint32_t a;
    asm("{ .reg .u64 t; cvta.to.shared.u64 t, %1; cvt.u32.u64 %0, t; }" : "=r"(a) : "l"(p));
    return a;
}
#define CP_ASYNC16(dst, src) \
    asm volatile("cp.async.ca.shared.global [%0], [%1], 16;" :: "r"(dst), "l"(src))
#define CP_COMMIT() asm volatile("cp.async.commit_group;")
#define CP_WAIT0()  asm volatile("cp.async.wait_group 0;")

// ---------------- Stage 1a: split-k partial GEMM (8 slices of 64 k) ----------------
// grid (96 rowtiles, 8 kslices), block 256. Block: 8 rows x 64 h x 64 k.
__global__ __launch_bounds__(256) void stage1a(
    const float* __restrict__ m, const float* __restrict__ W_in)
{
    __shared__ __align__(16) float m_s[8 * 64];      // 2 KB
    __shared__ __align__(16) float w_s[64 * 68];     // 17.4 KB (pad 68)
    int tid = threadIdx.x;
    int rbase = blockIdx.x * 8;
    int kc = blockIdx.y * 64;

    if (tid < 128) {
        int r = tid >> 4, c = (tid & 15) * 4;
        *(float4*)&m_s[r * 64 + c] =
            *(const float4*)(m + (size_t)(rbase + r) * 512 + kc + c);
    }
#pragma unroll
    for (int k = 0; k < 4; k++) {
        int idx4 = tid + k * 256;                    // 0..1023
        int h = idx4 >> 4, c = (idx4 & 15) * 4;
        *(float4*)&w_s[h * 68 + c] =
            *(const float4*)(W_in + (size_t)h * 512 + kc + c);
    }
    __syncthreads();

    int h = tid & 63, rg = tid >> 6;                 // rows rg and rg+4
    float acc0 = 0.f, acc1 = 0.f;
#pragma unroll
    for (int x = 0; x < 16; x++) {
        float4 wv = *(const float4*)&w_s[h * 68 + x * 4];   // conflict-free
        float4 m0 = *(const float4*)&m_s[rg * 64 + x * 4];  // broadcast
        float4 m1 = *(const float4*)&m_s[(rg + 4) * 64 + x * 4];
        acc0 = fmaf(wv.x, m0.x, acc0); acc0 = fmaf(wv.y, m0.y, acc0);
        acc0 = fmaf(wv.z, m0.z, acc0); acc0 = fmaf(wv.w, m0.w, acc0);
        acc1 = fmaf(wv.x, m1.x, acc1); acc1 = fmaf(wv.y, m1.y, acc1);
        acc1 = fmaf(wv.z, m1.z, acc1); acc1 = fmaf(wv.w, m1.w, acc1);
    }
    float* dst = g_part + (size_t)blockIdx.y * PSLICE;
    dst[(size_t)(rbase + rg) * 64 + h] = acc0;
    dst[(size_t)(rbase + rg + 4) * 64 + h] = acc1;
}

// ---------------- Stage 2 (fused reduce): t[row,p,y] = sum_x a[row,x]*Wo[p,x,y] ----------------
// grid (16 p-tiles, 24 row-tiles), block 256. Block: 8 p x 32 rows x 32 y.
// Reduces g_part (8 slices) -> a_s internally; blockIdx.x==0 also writes bv to g_ab.
__global__ __launch_bounds__(256) void stage2_t(
    const float* __restrict__ W_out, const float* __restrict__ b_in,
    const float* __restrict__ op_mask)
{
    __shared__ __align__(16) float w_s[8 * 1024];    // 32 KB
    __shared__ __align__(16) float a_s[32 * 32];
    int tid = threadIdx.x;
    int pbase = blockIdx.x * 8;
    int rbase = blockIdx.y * 32;

    const float4* wsrc = (const float4*)(W_out + (size_t)pbase * 1024);
    float4* wdst = (float4*)w_s;
#pragma unroll
    for (int k = 0; k < 8; k++) wdst[tid + k * 256] = wsrc[tid + k * 256];

    // a-half reduce: 32 rows x 32 cols over 8 slices
#pragma unroll
    for (int k = 0; k < 4; k++) {
        int e = tid + k * 256;           // 0..1023
        int r = e >> 5, c = e & 31;
        int gi = (rbase + r) * 64 + c;
        float s = 0.f;
#pragma unroll
        for (int sl = 0; sl < NSLICE; sl++) s += g_part[gi + sl * PSLICE];
        a_s[r * 32 + c] = (s + b_in[c]) * op_mask[rbase + r];
    }
    // bv-half reduce + write (one block column only)
    if (blockIdx.x == 0) {
#pragma unroll
        for (int k = 0; k < 4; k++) {
            int e = tid + k * 256;
            int r = e >> 5, c = e & 31;
            int gi = (rbase + r) * 64 + 32 + c;
            float s = 0.f;
#pragma unroll
            for (int sl = 0; sl < NSLICE; sl++) s += g_part[gi + sl * PSLICE];
            g_ab[gi] = (s + b_in[32 + c]) * op_mask[rbase + r];
        }
    }
    __syncthreads();

    int y = tid & 31, q = tid >> 5;      // lane=y, warp=p-within-tile (8 p)
    unsigned long long w2[16];
#pragma unroll
    for (int x2 = 0; x2 < 16; x2++) {
        w2[x2] = pack2(w_s[q * 1024 + (2 * x2 + 0) * 32 + y],
                       w_s[q * 1024 + (2 * x2 + 1) * 32 + y]);
    }
    float* dst = g_t + (size_t)rbase * 4096 + (size_t)(pbase + q) * 32 + y;
#pragma unroll 4
    for (int r = 0; r < 32; r++) {
        unsigned long long acc = 0ull;
#pragma unroll
        for (int xc = 0; xc < 8; xc++) {
            ulonglong2 a2 = *(const ulonglong2*)&a_s[r * 32 + xc * 4]; // broadcast
            fma2(acc, a2.x, w2[2 * xc + 0]);
            fma2(acc, a2.y, w2[2 * xc + 1]);
        }
        float lo, hi; unpack2(acc, lo, hi);
        dst[(size_t)r * 4096] = __uint_as_float(f2tf32(lo + hi));
    }
}

// ---------------- Stage 3 (warp MMA, tf32, cp.async pipelined) — exact R6/R10 ----------------
// grid (2, NN, BSZ): each CTA = 3 j-chunks of 64 for one (b,i).
// Warp grid 2(j) x 4(p): warp tile 32j x 32p. a_s double-buffered via cp.async.
#define S3PAD 36
__global__ __launch_bounds__(256, 3) void stage3_mma(
    const float* __restrict__ b_out, const float* __restrict__ op_norm,
    float* __restrict__ out)
{
    __shared__ __align__(16) uint32_t t_s[128 * S3PAD];     // 18.4 KB (tf32 bits)
    __shared__ __align__(16) uint32_t a_s[2][64 * S3PAD];   // 2 x 9.2 KB (raw fp32 bv)
    __shared__ float bo_s[128];

    int tid = threadIdx.x;
    int half = blockIdx.x;        // 0/1: j-chunks 0..2 / 3..5
    int i = blockIdx.y;
    int b = blockIdx.z;
    int row = b * NN + i;

    uint32_t t_base = smem_u32(t_s);
    uint32_t a_base = smem_u32(a_s);

    // async fill t row (16 KB, already tf32-rounded by stage2)
    const float* tsrc = g_t + (size_t)row * 4096;
#pragma unroll
    for (int k = 0; k < 4; k++) {
        int idx4 = tid + k * 256;
        int e = idx4 * 4, p = e >> 5, y = e & 31;
        CP_ASYNC16(t_base + (uint32_t)(p * S3PAD + y) * 4, tsrc + e);
    }
    // async fill a_s buf0 (chunk 0 of this half): raw fp32 bv
    const float* absrc = g_ab + (size_t)(b * NN) * 64;
    int jb0 = half * 192;
#pragma unroll
    for (int k = 0; k < 2; k++) {
        int idx4 = tid + k * 256;
        int j = idx4 >> 3, c = (idx4 & 7) * 4;
        CP_ASYNC16(a_base + (uint32_t)(j * S3PAD + c) * 4,
                   absrc + (size_t)(jb0 + j) * 64 + 32 + c);
    }
    CP_COMMIT();
    if (tid < 128) bo_s[tid] = b_out[tid];

    int wid = tid >> 5, lane = tid & 31;
    int g = lane >> 2, tg = lane & 3;
    int wm = wid & 1;          // j block of 32 (within 64-chunk)
    int wn = wid >> 1;         // p block of 32
    float norm = op_norm[b];

    for (int jc = 0; jc < 3; jc++) {
        int jbase = half * 192 + jc * 64;
        int buf = jc & 1;
        CP_WAIT0();
        __syncthreads();   // buf ready; all warps done with prev chunk (other buf)

        if (jc < 2) {      // prefetch next chunk into other buffer
            uint32_t dstb = a_base + (uint32_t)((buf ^ 1) * 64 * S3PAD) * 4;
#pragma unroll
            for (int k = 0; k < 2; k++) {
                int idx4 = tid + k * 256;
                int j = idx4 >> 3, c = (idx4 & 7) * 4;
                CP_ASYNC16(dstb + (uint32_t)(j * S3PAD + c) * 4,
                           absrc + (size_t)(jbase + 64 + j) * 64 + 32 + c);
            }
            CP_COMMIT();
        } else {
            CP_COMMIT();   // keep wait_group balanced
        }

        const uint32_t* ab = a_s[buf];
        float acc[2][4][4];
#pragma unroll
        for (int mt = 0; mt < 2; mt++)
#pragma unroll
            for (int nt = 0; nt < 4; nt++)
#pragma unroll
                for (int r = 0; r < 4; r++) acc[mt][nt][r] = 0.f;

#pragma unroll
        for (int ks = 0; ks < 4; ks++) {
            int kk = ks * 8;
            uint32_t af[2][4];
#pragma unroll
            for (int mt = 0; mt < 2; mt++) {
                int r0 = wm * 32 + mt * 16;
                af[mt][0] = f2tf32(__uint_as_float(ab[(r0 + g) * S3PAD + kk + tg]));
                af[mt][1] = f2tf32(__uint_as_float(ab[(r0 + 8 + g) * S3PAD + kk + tg]));
                af[mt][2] = f2tf32(__uint_as_float(ab[(r0 + g) * S3PAD + kk + tg + 4]));
                af[mt][3] = f2tf32(__uint_as_float(ab[(r0 + 8 + g) * S3PAD + kk + tg + 4]));
            }
            uint32_t bf[4][2];
#pragma unroll
            for (int nt = 0; nt < 4; nt++) {
                int cc = wn * 32 + nt * 8 + g;
                bf[nt][0] = t_s[cc * S3PAD + kk + tg];
                bf[nt][1] = t_s[cc * S3PAD + kk + tg + 4];
            }
#pragma unroll
            for (int mt = 0; mt < 2; mt++)
#pragma unroll
                for (int nt = 0; nt < 4; nt++)
                    mma_tf32(acc[mt][nt], af[mt], bf[nt]);
        }

        // epilogue: z = acc*norm + b_out[p]*norm (streaming stores)
        size_t obase = ((size_t)row * NN + jbase) * DPAIR;
#pragma unroll
        for (int mt = 0; mt < 2; mt++) {
            int j0 = wm * 32 + mt * 16 + g;
#pragma unroll
            for (int nt = 0; nt < 4; nt++) {
                int p = wn * 32 + nt * 8 + 2 * tg;
                float bz0 = bo_s[p] * norm, bz1 = bo_s[p + 1] * norm;
                float2 v0 = make_float2(fmaf(acc[mt][nt][0], norm, bz0),
                                        fmaf(acc[mt][nt][1], norm, bz1));
                float2 v1 = make_float2(fmaf(acc[mt][nt][2], norm, bz0),
                                        fmaf(acc[mt][nt][3], norm, bz1));
                __stcs((float2*)(out + obase + (size_t)j0 * DPAIR + p), v0);
                __stcs((float2*)(out + obase + (size_t)(j0 + 8) * DPAIR + p), v1);
            }
        }
    }
}

// ---------------- launch ----------------
extern "C" void kernel_launch(void* const* d_in, const int* in_sizes, int n_in,
                              void* d_out, int out_size)
{
    const float* m       = (const float*)d_in[0];
    const float* op_mask = (const float*)d_in[1];
    const float* op_norm = (const float*)d_in[2];
    const float* W_in    = (const float*)d_in[3];
    const float* b_in    = (const float*)d_in[4];
    const float* W_out   = (const float*)d_in[5];
    const float* b_out   = (const float*)d_in[6];
    float* out = (float*)d_out;

    stage1a<<<dim3(96, NSLICE), 256>>>(m, W_in);
    stage2_t<<<dim3(16, 24), 256>>>(W_out, b_in, op_mask);
    stage3_mma<<<dim3(2, NN, BSZ), 256>>>(b_out, op_norm, out);
}

// round 14
// speedup vs baseline: 1.1413x; 1.0101x over previous
#include <cuda_runtime.h>
#include <cuda_bf16.h>
#include <cstdint>

// Shapes (fixed by the problem)
#define BSZ    2
#define NN     384
#define DATOM  512
#define DPAIR  128
#define DHID   32
#define NROWS  (BSZ*NN)          // 768
#define PSLICE (NROWS*64)        // 49152
#define NSLICE 8                 // split-k slices (64 k each)

// Scratch (no cudaMalloc allowed)
__device__ float g_ab[NROWS * 64];            // bv half used by stage3 (cols 32..63)
__device__ float g_t [NROWS * DPAIR * DHID];  // t[row][p][y] (tf32-rounded bits)
__device__ float g_part[NSLICE * PSLICE];     // stage1 split-k partials

// ---------------- f32x2 packed-FMA helpers (sm_103a) ----------------
__device__ __forceinline__ unsigned long long pack2(float x, float y) {
    unsigned long long r;
    asm("mov.b64 %0,{%1,%2};" : "=l"(r) : "f"(x), "f"(y));
    return r;
}
__device__ __forceinline__ void unpack2(unsigned long long v, float& x, float& y) {
    asm("mov.b64 {%0,%1},%2;" : "=f"(x), "=f"(y) : "l"(v));
}
__device__ __forceinline__ void fma2(unsigned long long& d,
                                     unsigned long long a,
                                     unsigned long long b) {
    asm("fma.rn.f32x2 %0,%1,%2,%0;" : "+l"(d) : "l"(a), "l"(b));
}

// ---------------- tf32 / async helpers ----------------
__device__ __forceinline__ uint32_t f2tf32(float f) {
    uint32_t u;
    asm("cvt.rna.tf32.f32 %0, %1;" : "=r"(u) : "f"(f));
    return u;
}
__device__ __forceinline__ void mma_tf32(float c[4], const uint32_t a[4],
                                         const uint32_t b[2]) {
    asm("mma.sync.aligned.m16n8k8.row.col.f32.tf32.tf32.f32 "
        "{%0,%1,%2,%3}, {%4,%5,%6,%7}, {%8,%9}, {%0,%1,%2,%3};"
        : "+f"(c[0]), "+f"(c[1]), "+f"(c[2]), "+f"(c[3])
        : "r"(a[0]), "r"(a[1]), "r"(a[2]), "r"(a[3]), "r"(b[0]), "r"(b[1]));
}
__device__ __forceinline__ uint32_t smem_u32(const void* p) {
    uint32_t a;
    asm("{ .reg .u64 t; cvta.to.shared.u64 t, %1; cvt.u32.u64 %0, t; }" : "=r"(a) : "l"(p));
    return a;
}
#define CP_ASYNC16(dst, src) \
    asm volatile("cp.async.ca.shared.global [%0], [%1], 16;" :: "r"(dst), "l"(src))
#define CP_COMMIT() asm volatile("cp.async.commit_group;")
#define CP_WAIT0()  asm volatile("cp.async.wait_group 0;")

// ---------------- Stage 1a: split-k partial GEMM (8 slices of 64 k, f32x2) ----------------
// grid (96 rowtiles, 8 kslices), block 256. Block: 8 rows x 64 h x 64 k.
__global__ __launch_bounds__(256) void stage1a(
    const float* __restrict__ m, const float* __restrict__ W_in)
{
    __shared__ __align__(16) float m_s[8 * 64];      // 2 KB
    __shared__ __align__(16) float w_s[64 * 68];     // 17.4 KB (pad 68)
    int tid = threadIdx.x;
    int rbase = blockIdx.x * 8;
    int kc = blockIdx.y * 64;

    if (tid < 128) {
        int r = tid >> 4, c = (tid & 15) * 4;
        *(float4*)&m_s[r * 64 + c] =
            *(const float4*)(m + (size_t)(rbase + r) * 512 + kc + c);
    }
#pragma unroll
    for (int k = 0; k < 4; k++) {
        int idx4 = tid + k * 256;                    // 0..1023
        int h = idx4 >> 4, c = (idx4 & 15) * 4;
        *(float4*)&w_s[h * 68 + c] =
            *(const float4*)(W_in + (size_t)h * 512 + kc + c);
    }
    __syncthreads();

    int h = tid & 63, rg = tid >> 6;                 // rows rg and rg+4
    unsigned long long acc0 = 0ull, acc1 = 0ull;     // {even-k, odd-k} lanes
#pragma unroll
    for (int x = 0; x < 16; x++) {
        ulonglong2 wv = *(const ulonglong2*)&w_s[h * 68 + x * 4];    // conflict-free
        ulonglong2 m0 = *(const ulonglong2*)&m_s[rg * 64 + x * 4];   // broadcast
        ulonglong2 m1 = *(const ulonglong2*)&m_s[(rg + 4) * 64 + x * 4];
        fma2(acc0, wv.x, m0.x); fma2(acc0, wv.y, m0.y);
        fma2(acc1, wv.x, m1.x); fma2(acc1, wv.y, m1.y);
    }
    float l0, h0, l1, h1;
    unpack2(acc0, l0, h0); unpack2(acc1, l1, h1);
    float* dst = g_part + (size_t)blockIdx.y * PSLICE;
    dst[(size_t)(rbase + rg) * 64 + h] = l0 + h0;
    dst[(size_t)(rbase + rg + 4) * 64 + h] = l1 + h1;
}

// ---------------- Stage 2 (fused reduce): t[row,p,y] = sum_x a[row,x]*Wo[p,x,y] ----------------
// grid (16 p-tiles, 24 row-tiles), block 256. Block: 8 p x 32 rows x 32 y.
// Reduces g_part (8 slices) -> a_s internally; blockIdx.x==0 also writes bv to g_ab.
__global__ __launch_bounds__(256) void stage2_t(
    const float* __restrict__ W_out, const float* __restrict__ b_in,
    const float* __restrict__ op_mask)
{
    __shared__ __align__(16) float w_s[8 * 1024];    // 32 KB
    __shared__ __align__(16) float a_s[32 * 32];
    int tid = threadIdx.x;
    int pbase = blockIdx.x * 8;
    int rbase = blockIdx.y * 32;

    const float4* wsrc = (const float4*)(W_out + (size_t)pbase * 1024);
    float4* wdst = (float4*)w_s;
#pragma unroll
    for (int k = 0; k < 8; k++) wdst[tid + k * 256] = wsrc[tid + k * 256];

    // a-half reduce: 32 rows x 32 cols over 8 slices
#pragma unroll
    for (int k = 0; k < 4; k++) {
        int e = tid + k * 256;           // 0..1023
        int r = e >> 5, c = e & 31;
        int gi = (rbase + r) * 64 + c;
        float s = 0.f;
#pragma unroll
        for (int sl = 0; sl < NSLICE; sl++) s += g_part[gi + sl * PSLICE];
        a_s[r * 32 + c] = (s + b_in[c]) * op_mask[rbase + r];
    }
    // bv-half reduce + write (one block column only)
    if (blockIdx.x == 0) {
#pragma unroll
        for (int k = 0; k < 4; k++) {
            int e = tid + k * 256;
            int r = e >> 5, c = e & 31;
            int gi = (rbase + r) * 64 + 32 + c;
            float s = 0.f;
#pragma unroll
            for (int sl = 0; sl < NSLICE; sl++) s += g_part[gi + sl * PSLICE];
            g_ab[gi] = (s + b_in[32 + c]) * op_mask[rbase + r];
        }
    }
    __syncthreads();

    int y = tid & 31, q = tid >> 5;      // lane=y, warp=p-within-tile (8 p)
    unsigned long long w2[16];
#pragma unroll
    for (int x2 = 0; x2 < 16; x2++) {
        w2[x2] = pack2(w_s[q * 1024 + (2 * x2 + 0) * 32 + y],
                       w_s[q * 1024 + (2 * x2 + 1) * 32 + y]);
    }
    float* dst = g_t + (size_t)rbase * 4096 + (size_t)(pbase + q) * 32 + y;
#pragma unroll 4
    for (int r = 0; r < 32; r++) {
        unsigned long long acc = 0ull;
#pragma unroll
        for (int xc = 0; xc < 8; xc++) {
            ulonglong2 a2 = *(const ulonglong2*)&a_s[r * 32 + xc * 4]; // broadcast
            fma2(acc, a2.x, w2[2 * xc + 0]);
            fma2(acc, a2.y, w2[2 * xc + 1]);
        }
        float lo, hi; unpack2(acc, lo, hi);
        dst[(size_t)r * 4096] = __uint_as_float(f2tf32(lo + hi));
    }
}

// ---------------- Stage 3 (warp MMA, tf32, cp.async pipelined) — exact R6/R10 ----------------
// grid (2, NN, BSZ): each CTA = 3 j-chunks of 64 for one (b,i).
// Warp grid 2(j) x 4(p): warp tile 32j x 32p. a_s double-buffered via cp.async.
#define S3PAD 36
__global__ __launch_bounds__(256, 3) void stage3_mma(
    const float* __restrict__ b_out, const float* __restrict__ op_norm,
    float* __restrict__ out)
{
    __shared__ __align__(16) uint32_t t_s[128 * S3PAD];     // 18.4 KB (tf32 bits)
    __shared__ __align__(16) uint32_t a_s[2][64 * S3PAD];   // 2 x 9.2 KB (raw fp32 bv)
    __shared__ float bo_s[128];

    int tid = threadIdx.x;
    int half = blockIdx.x;        // 0/1: j-chunks 0..2 / 3..5
    int i = blockIdx.y;
    int b = blockIdx.z;
    int row = b * NN + i;

    uint32_t t_base = smem_u32(t_s);
    uint32_t a_base = smem_u32(a_s);

    // async fill t row (16 KB, already tf32-rounded by stage2)
    const float* tsrc = g_t + (size_t)row * 4096;
#pragma unroll
    for (int k = 0; k < 4; k++) {
        int idx4 = tid + k * 256;
        int e = idx4 * 4, p = e >> 5, y = e & 31;
        CP_ASYNC16(t_base + (uint32_t)(p * S3PAD + y) * 4, tsrc + e);
    }
    // async fill a_s buf0 (chunk 0 of this half): raw fp32 bv
    const float* absrc = g_ab + (size_t)(b * NN) * 64;
    int jb0 = half * 192;
#pragma unroll
    for (int k = 0; k < 2; k++) {
        int idx4 = tid + k * 256;
        int j = idx4 >> 3, c = (idx4 & 7) * 4;
        CP_ASYNC16(a_base + (uint32_t)(j * S3PAD + c) * 4,
                   absrc + (size_t)(jb0 + j) * 64 + 32 + c);
    }
    CP_COMMIT();
    if (tid < 128) bo_s[tid] = b_out[tid];

    int wid = tid >> 5, lane = tid & 31;
    int g = lane >> 2, tg = lane & 3;
    int wm = wid & 1;          // j block of 32 (within 64-chunk)
    int wn = wid >> 1;         // p block of 32
    float norm = op_norm[b];

    for (int jc = 0; jc < 3; jc++) {
        int jbase = half * 192 + jc * 64;
        int buf = jc & 1;
        CP_WAIT0();
        __syncthreads();   // buf ready; all warps done with prev chunk (other buf)

        if (jc < 2) {      // prefetch next chunk into other buffer
            uint32_t dstb = a_base + (uint32_t)((buf ^ 1) * 64 * S3PAD) * 4;
#pragma unroll
            for (int k = 0; k < 2; k++) {
                int idx4 = tid + k * 256;
                int j = idx4 >> 3, c = (idx4 & 7) * 4;
                CP_ASYNC16(dstb + (uint32_t)(j * S3PAD + c) * 4,
                           absrc + (size_t)(jbase + 64 + j) * 64 + 32 + c);
            }
            CP_COMMIT();
        } else {
            CP_COMMIT();   // keep wait_group balanced
        }

        const uint32_t* ab = a_s[buf];
        float acc[2][4][4];
#pragma unroll
        for (int mt = 0; mt < 2; mt++)
#pragma unroll
            for (int nt = 0; nt < 4; nt++)
#pragma unroll
                for (int r = 0; r < 4; r++) acc[mt][nt][r] = 0.f;

#pragma unroll
        for (int ks = 0; ks < 4; ks++) {
            int kk = ks * 8;
            uint32_t af[2][4];
#pragma unroll
            for (int mt = 0; mt < 2; mt++) {
                int r0 = wm * 32 + mt * 16;
                af[mt][0] = f2tf32(__uint_as_float(ab[(r0 + g) * S3PAD + kk + tg]));
                af[mt][1] = f2tf32(__uint_as_float(ab[(r0 + 8 + g) * S3PAD + kk + tg]));
                af[mt][2] = f2tf32(__uint_as_float(ab[(r0 + g) * S3PAD + kk + tg + 4]));
                af[mt][3] = f2tf32(__uint_as_float(ab[(r0 + 8 + g) * S3PAD + kk + tg + 4]));
            }
            uint32_t bf[4][2];
#pragma unroll
            for (int nt = 0; nt < 4; nt++) {
                int cc = wn * 32 + nt * 8 + g;
                bf[nt][0] = t_s[cc * S3PAD + kk + tg];
                bf[nt][1] = t_s[cc * S3PAD + kk + tg + 4];
            }
#pragma unroll
            for (int mt = 0; mt < 2; mt++)
#pragma unroll
                for (int nt = 0; nt < 4; nt++)
                    mma_tf32(acc[mt][nt], af[mt], bf[nt]);
        }

        // epilogue: z = acc*norm + b_out[p]*norm (streaming stores)
        size_t obase = ((size_t)row * NN + jbase) * DPAIR;
#pragma unroll
        for (int mt = 0; mt < 2; mt++) {
            int j0 = wm * 32 + mt * 16 + g;
#pragma unroll
            for (int nt = 0; nt < 4; nt++) {
                int p = wn * 32 + nt * 8 + 2 * tg;
                float bz0 = bo_s[p] * norm, bz1 = bo_s[p + 1] * norm;
                float2 v0 = make_float2(fmaf(acc[mt][nt][0], norm, bz0),
                                        fmaf(acc[mt][nt][1], norm, bz1));
                float2 v1 = make_float2(fmaf(acc[mt][nt][2], norm, bz0),
                                        fmaf(acc[mt][nt][3], norm, bz1));
                __stcs((float2*)(out + obase + (size_t)j0 * DPAIR + p), v0);
                __stcs((float2*)(out + obase + (size_t)(j0 + 8) * DPAIR + p), v1);
            }
        }
    }
}

// ---------------- launch ----------------
extern "C" void kernel_launch(void* const* d_in, const int* in_sizes, int n_in,
                              void* d_out, int out_size)
{
    const float* m       = (const float*)d_in[0];
    const float* op_mask = (const float*)d_in[1];
    const float* op_norm = (const float*)d_in[2];
    const float* W_in    = (const float*)d_in[3];
    const float* b_in    = (const float*)d_in[4];
    const float* W_out   = (const float*)d_in[5];
    const float* b_out   = (const float*)d_in[6];
    float* out = (float*)d_out;

    stage1a<<<dim3(96, NSLICE), 256>>>(m, W_in);
    stage2_t<<<dim3(16, 24), 256>>>(W_out, b_in, op_mask);
    stage3_mma<<<dim3(2, NN, BSZ), 256>>>(b_out, op_norm, out);
}